// round 10
// baseline (speedup 1.0000x reference)
#include <cuda_runtime.h>
#include <cuda_bf16.h>
#include <math.h>

#define E      256
#define H1     32
#define H2     16
#define MAXD   1024
#define MAXN   (1024*100)

typedef unsigned long long ull;

// ---------------- device scratch ----------------
__device__ int      g_dagids[MAXN];
__device__ float    g_yop[MAXD * H1];
__device__ float    g_ypr[MAXD * H1];
__device__ float    g_czop[H1];
__device__ float    g_czpr[H1];
__device__ float    g_partials[2048];
__device__ ull      g_wpk[4096];       // opW1 x-part packed: ull2[k4][lane]

__device__ __forceinline__ ull ffma2(ull a, ull b, ull c) {
    ull d;
    asm("fma.rn.f32x2 %0, %1, %2, %3;" : "=l"(d) : "l"(a), "l"(b), "l"(c));
    return d;
}
__device__ __forceinline__ ull pack2(float lo, float hi) {
    return (ull)__float_as_uint(lo) | ((ull)__float_as_uint(hi) << 32);
}
__device__ __forceinline__ float unpack_sum(ull v) {
    return __uint_as_float((unsigned)(v & 0xffffffffu)) +
           __uint_as_float((unsigned)(v >> 32));
}

// ---------------- K1 (512 thr): y-precompute + dagfill + repack + cz ----------------
#define PRE_SMEM (32768 + 32768 + 8192)
__global__ void __launch_bounds__(512)
k_pre(const float* __restrict__ y,
      const float* __restrict__ opW1, const float* __restrict__ opb1,
      const float* __restrict__ prW1, const float* __restrict__ prb1,
      const float* __restrict__ z,
      const int* __restrict__ num_ops, int D)
{
    extern __shared__ unsigned char sm_raw[];
    int nbY = D / 8;
    int nbF = D / 16;
    int tid = threadIdx.x;
    int b = blockIdx.x;

    if (b < nbY) {
        float* swop = (float*)sm_raw;                 // [256][32]
        float* swpr = (float*)(sm_raw + 32768);       // [256][32]
        float* sy   = (float*)(sm_raw + 65536);       // [8][256]
        int d0 = b * 8;
        {
            const float4* s1 = (const float4*)(opW1 + E * H1);
            const float4* s2 = (const float4*)(prW1 + H1);
            float4* d1 = (float4*)swop;
            float4* d2 = (float4*)swpr;
            #pragma unroll 4
            for (int i = tid; i < 2048; i += 512) { d1[i] = s1[i]; d2[i] = s2[i]; }
            const float4* ys = (const float4*)(y + (size_t)d0 * E);
            float4* yd = (float4*)sy;
            if (tid < 512) yd[tid] = ys[tid];
        }
        __syncthreads();
        int warp = tid >> 5, lane = tid & 31;
        int dag = warp & 7, br = warp >> 3;
        const float* w = br ? swpr : swop;
        const float* yr = sy + dag * 256;
        float a0 = 0.f, a1 = 0.f, a2 = 0.f, a3 = 0.f;
        #pragma unroll 8
        for (int k = 0; k < 256; k += 4) {
            a0 = fmaf(yr[k],     w[(k)     * 32 + lane], a0);
            a1 = fmaf(yr[k + 1], w[(k + 1) * 32 + lane], a1);
            a2 = fmaf(yr[k + 2], w[(k + 2) * 32 + lane], a2);
            a3 = fmaf(yr[k + 3], w[(k + 3) * 32 + lane], a3);
        }
        float v = (a0 + a1) + (a2 + a3);
        if (br) g_ypr[(d0 + dag) * H1 + lane] = v;
        else    g_yop[(d0 + dag) * H1 + lane] = v;
        return;
    }
    if (b < nbY + nbF) {
        __shared__ int sc[256];
        __shared__ int sstart[17];
        int fb = b - nbY, d0 = fb * 16;
        if (tid < 256) {
            int a = 0;
            #pragma unroll
            for (int q = 0; q < 4; q++) {
                int idx = tid * 4 + q;
                a += (idx < D) ? num_ops[idx] : 0;
            }
            sc[tid] = a;
        }
        __syncthreads();
        #pragma unroll
        for (int off = 1; off < 256; off <<= 1) {
            int v = (tid < 256 && tid >= off) ? sc[tid - off] : 0;
            __syncthreads();
            if (tid < 256) sc[tid] += v;
            __syncthreads();
        }
        if (tid <= 16) {
            int d = d0 + tid;
            int s = (d >> 2) ? sc[(d >> 2) - 1] : 0;
            for (int q = d & ~3; q < d; q++) s += num_ops[q];
            sstart[tid] = s;
        }
        __syncthreads();
        for (int dd = 0; dd < 16; dd++) {
            int s = sstart[dd], e = sstart[dd + 1];
            for (int i = s + tid; i < e; i += 512) g_dagids[i] = d0 + dd;
        }
        return;
    }
    if (b == nbY + nbF) {
        for (int idx = tid; idx < 4096; idx += 512) {
            int p = idx >> 1, c = idx & 1;
            int k4 = p >> 5, j = p & 31;
            g_wpk[idx] = pack2(opW1[(4 * k4 + 2 * c) * H1 + j],
                               opW1[(4 * k4 + 2 * c + 1) * H1 + j]);
        }
        return;
    }
    {
        __shared__ float sred[256];
        int br = b - (nbY + nbF + 1);
        const float* W  = br ? prW1 : opW1;
        const float* b1 = br ? prb1 : opb1;
        int off = br ? (1 + E) : (2 * E);
        if (tid < 256) {
            int j = tid & 31, c = tid >> 5;
            float a0 = 0.f, a1 = 0.f, a2 = 0.f, a3 = 0.f;
            #pragma unroll
            for (int r = 0; r < 8; r++) {
                int k = c * 32 + r * 4;
                a0 = fmaf(z[k],     W[(off + k) * H1 + j],     a0);
                a1 = fmaf(z[k + 1], W[(off + k + 1) * H1 + j], a1);
                a2 = fmaf(z[k + 2], W[(off + k + 2) * H1 + j], a2);
                a3 = fmaf(z[k + 3], W[(off + k + 3) * H1 + j], a3);
            }
            sred[tid] = (a0 + a1) + (a2 + a3);
        }
        __syncthreads();
        if (tid < 32) {
            float s = b1[tid];
            #pragma unroll
            for (int cc = 0; cc < 8; cc++) s += sred[tid + 32 * cc];
            if (br) g_czpr[tid] = s;
            else    g_czop[tid] = s;
        }
    }
}

// ---------------- K2: prlvl blocks first, then op MLP (cp.async ring-3) ----------------
#define OP_SW    0                       // 4096 ull = 32768
#define OP_SX    32768                   // 3 x 1024 float4 = 49152
#define OP_SH    81920                   // 8 warps x 16*33 f = 16896
#define OP_SW2   98816                   // 512 f = 2048
#define OP_SW3   100864
#define OP_SB2   100928
#define OP_SRED  100992
#define OP_TOTAL 101024

#define OP_ISSUE(cc) do {                                                        \
    _Pragma("unroll")                                                            \
    for (int r = 0; r < 4; r++) {                                                \
        unsigned sa = sidx[r] + ((cc) % 3) * 16384;                              \
        const float4* ga = gp[r] + (cc) * 8;                                     \
        asm volatile("cp.async.ca.shared.global [%0], [%1], 16;"                 \
                     :: "r"(sa), "l"(ga) : "memory");                            \
    }                                                                            \
    asm volatile("cp.async.commit_group;" ::: "memory");                         \
} while (0)

#define OP_CHUNK(cc, wn) do {                                                    \
    asm volatile("cp.async.wait_group %0;" :: "n"(wn) : "memory");               \
    __syncthreads();                                                             \
    const ulonglong2* xq = (const ulonglong2*)(sx + ((cc) % 3) * 1024)           \
                           + warp * 16 * 8;                                      \
    _Pragma("unroll")                                                            \
    for (int k4 = 0; k4 < 8; k4++) {                                             \
        ulonglong2 w = wq[((cc) * 8 + k4) * 32 + lane];                          \
        _Pragma("unroll")                                                        \
        for (int u = 0; u < 16; u++) {                                           \
            ulonglong2 xv = xq[u * 8 + k4];                                      \
            acc[u] = ffma2(xv.x, w.x, acc[u]);                                   \
            acc[u] = ffma2(xv.y, w.y, acc[u]);                                   \
        }                                                                        \
    }                                                                            \
    if ((cc) + 2 < 8) OP_ISSUE((cc) + 2);                                        \
} while (0)

__global__ void __launch_bounds__(256, 2)
k_op(const float* __restrict__ x,
     const float* __restrict__ opW2, const float* __restrict__ opb2,
     const float* __restrict__ opW3, const float* __restrict__ opb3,
     const float* __restrict__ omsk, int n, int nb_pr,
     const float* __restrict__ prW1, const float* __restrict__ prW2,
     const float* __restrict__ prb2, const float* __restrict__ prW3,
     const float* __restrict__ prb3, const float* __restrict__ pmsk,
     float* __restrict__ out_ops, float* __restrict__ out_pr, int W)
{
    extern __shared__ unsigned char sm_raw[];
    int tid = threadIdx.x;

    if (blockIdx.x < nb_pr) {
        // ---------- prlvl: 4 dags per block, W=64 workers ----------
        float* sm   = (float*)sm_raw;
        float* sYP  = sm;          // [4][32]
        float* sr0  = sm + 128;
        float* sW2p = sm + 160;    // [512]
        float* sW3p = sm + 672;
        float* sb2p = sm + 688;
        float* red  = sm + 704;    // [4][64]
        int pb = blockIdx.x;
        int d0 = pb * 4, g = tid >> 6, wk = tid & 63;
        int dag = d0 + g;

        if (tid < 128) {
            int gg = tid >> 5, j = tid & 31;
            sYP[gg * 32 + j] = g_ypr[(d0 + gg) * H1 + j] + g_czpr[j];
        }
        if (tid < H1) sr0[tid] = prW1[tid];
        for (int i = tid; i < H1 * H2; i += 256) sW2p[i] = prW2[i];
        if (tid < H2) { sW3p[tid] = prW3[tid]; sb2p[tid] = prb2[tid]; }
        __syncthreads();

        float lim = (float)(wk + 1);
        float h2[H2];
        #pragma unroll
        for (int m = 0; m < H2; m++) h2[m] = sb2p[m];
        #pragma unroll 4
        for (int j = 0; j < H1; j++) {
            float h1 = fmaxf(sYP[g * 32 + j] + lim * sr0[j], 0.f);
            #pragma unroll
            for (int m = 0; m < H2; m++) h2[m] += h1 * sW2p[j * H2 + m];
        }
        float lg = prb3[0];
        #pragma unroll
        for (int m = 0; m < H2; m++) lg += fmaxf(h2[m], 0.f) * sW3p[m];
        lg -= (1.f - pmsk[(size_t)dag * W + wk]) * 1000.f;

        red[g * 64 + wk] = lg;
        __syncthreads();
        for (int st = 32; st > 0; st >>= 1) {
            if (wk < st) red[g * 64 + wk] = fmaxf(red[g * 64 + wk], red[g * 64 + wk + st]);
            __syncthreads();
        }
        float mx = red[g * 64];
        __syncthreads();
        float ev = expf(lg - mx);
        red[g * 64 + wk] = ev;
        __syncthreads();
        for (int st = 32; st > 0; st >>= 1) {
            if (wk < st) red[g * 64 + wk] += red[g * 64 + wk + st];
            __syncthreads();
        }
        out_pr[(size_t)dag * W + wk] = ev / red[g * 64];
        return;
    }

    // ---------- op branch: 128 ops/block, 8 chunks x 32 cols, cp.async ring-3 ----------
    ull*    sw   = (ull*)(sm_raw + OP_SW);
    float4* sx   = (float4*)(sm_raw + OP_SX);
    float*  sH   = (float*)(sm_raw + OP_SH);
    float*  sW2  = (float*)(sm_raw + OP_SW2);
    float*  sW3  = (float*)(sm_raw + OP_SW3);
    float*  sb2  = (float*)(sm_raw + OP_SB2);
    float*  sRed = (float*)(sm_raw + OP_SRED);

    int ob = blockIdx.x - nb_pr;
    int base = ob * 128;
    int warp = tid >> 5, lane = tid & 31;
    const float4* xg = (const float4*)x;
    bool full = (base + 128 <= n);

    // per-thread staging addresses: idx = tid + 256*r -> (op = idx>>3, col = idx&7)
    unsigned sm_base;
    asm("{ .reg .u64 t; cvta.to.shared.u64 t, %1; cvt.u32.u64 %0, t; }"
        : "=r"(sm_base) : "l"((void*)sx));
    const float4* gp[4];
    unsigned sidx[4];
    #pragma unroll
    for (int r = 0; r < 4; r++) {
        int idx = tid + 256 * r;
        int op = idx >> 3, col = idx & 7;
        int gi = full ? (base + op) : min(base + op, n - 1);
        gp[r] = xg + (size_t)gi * 64 + col;
        sidx[r] = sm_base + (unsigned)idx * 16;
    }
    OP_ISSUE(0);
    OP_ISSUE(1);

    // stage packed W1 + layer-2/3 weights (overlaps with async x loads)
    {
        const float4* ws = (const float4*)g_wpk;
        float4* wd = (float4*)sw;
        #pragma unroll 4
        for (int i = tid; i < 2048; i += 256) wd[i] = ws[i];
    }
    for (int i = tid; i < H1 * H2; i += 256) sW2[i] = opW2[i];
    if (tid < H2) { sW3[tid] = opW3[tid]; sb2[tid] = opb2[tid]; }

    ull acc[16];
    #pragma unroll
    for (int u = 0; u < 16; u++) acc[u] = 0ull;

    const ulonglong2* wq = (const ulonglong2*)sw;
    OP_CHUNK(0, 1);
    OP_CHUNK(1, 1);
    OP_CHUNK(2, 1);
    OP_CHUNK(3, 1);
    OP_CHUNK(4, 1);
    OP_CHUNK(5, 1);
    OP_CHUNK(6, 1);
    OP_CHUNK(7, 0);

    // epilogue: add y+cz, relu, transpose via smem
    float* sHw = sH + warp * (16 * 33);
    {
        float czv = g_czop[lane];
        #pragma unroll
        for (int u = 0; u < 16; u++) {
            int i = full ? (base + warp * 16 + u) : min(base + warp * 16 + u, n - 1);
            float ypc = g_yop[g_dagids[i] * H1 + lane] + czv;
            sHw[u * 33 + lane] = fmaxf(unpack_sum(acc[u]) + ypc, 0.f);
        }
    }
    __syncwarp();

    // layers 2+3: lane -> (op o2 = lane>>1, neuron half m2 = lane&1)
    int o2 = lane >> 1, m2 = lane & 1;
    float h2[8];
    #pragma unroll
    for (int q = 0; q < 8; q++) h2[q] = sb2[m2 * 8 + q];
    const float* hrow = sHw + o2 * 33;
    #pragma unroll 8
    for (int j = 0; j < H1; j++) {
        float h = hrow[j];
        #pragma unroll
        for (int q = 0; q < 8; q++) h2[q] += h * sW2[j * H2 + m2 * 8 + q];
    }
    float part = 0.f;
    #pragma unroll
    for (int q = 0; q < 8; q++) part += fmaxf(h2[q], 0.f) * sW3[m2 * 8 + q];
    part += __shfl_xor_sync(0xffffffffu, part, 1);

    float e = 0.f;
    {
        int i = base + warp * 16 + o2;
        if (m2 == 0 && i < n) {
            float lg = part + opb3[0] - (1.f - omsk[i]) * 1000.f;
            e = expf(lg);
            out_ops[i] = e;
        }
    }
    e += __shfl_xor_sync(0xffffffffu, e, 1);
    e += __shfl_xor_sync(0xffffffffu, e, 2);
    e += __shfl_xor_sync(0xffffffffu, e, 4);
    e += __shfl_xor_sync(0xffffffffu, e, 8);
    e += __shfl_xor_sync(0xffffffffu, e, 16);
    if (lane == 0) sRed[warp] = e;
    __syncthreads();
    if (tid == 0) {
        float sum = 0.f;
        #pragma unroll
        for (int w = 0; w < 8; w++) sum += sRed[w];
        g_partials[ob] = sum;
    }
}

// ---------------- K3: reduce partials + normalize (float4) ----------------
__global__ void __launch_bounds__(256)
k_norm(float* __restrict__ out_ops, int n, int nb_op)
{
    __shared__ float red[256];
    int t = threadIdx.x;
    float s = 0.f;
    for (int q = t; q < nb_op; q += 256) s += g_partials[q];
    red[t] = s;
    __syncthreads();
    for (int st = 128; st > 0; st >>= 1) {
        if (t < st) red[t] += red[t + st];
        __syncthreads();
    }
    float inv = 1.f / red[0];
    int n4 = n >> 2;
    float4* o4 = (float4*)out_ops;
    for (int i = blockIdx.x * 256 + t; i < n4; i += gridDim.x * 256) {
        float4 v = o4[i];
        v.x *= inv; v.y *= inv; v.z *= inv; v.w *= inv;
        o4[i] = v;
    }
    if (blockIdx.x == 0) {
        for (int i = (n & ~3) + t; i < n; i += 256) out_ops[i] *= inv;
    }
}

// ---------------- launch ----------------
extern "C" void kernel_launch(void* const* d_in, const int* in_sizes, int n_in,
                              void* d_out, int out_size)
{
    int ix = -1;
    for (int i = 0; i < n_in; i++) {
        if (in_sizes[i] == MAXN * E) { ix = i; break; }
    }
    if (ix < 0) return;

    const int*   num_ops = (const int*)d_in[0];
    int D = in_sizes[0];
    const float* x    = (const float*)d_in[ix + 0];
    const float* y    = (const float*)d_in[ix + 1];
    const float* z    = (const float*)d_in[ix + 2];
    const float* omsk = (const float*)d_in[ix + 3];
    const float* pmsk = (const float*)d_in[ix + 4];
    const float* opW1 = (const float*)d_in[ix + 5];
    const float* opb1 = (const float*)d_in[ix + 6];
    const float* opW2 = (const float*)d_in[ix + 7];
    const float* opb2 = (const float*)d_in[ix + 8];
    const float* opW3 = (const float*)d_in[ix + 9];
    const float* opb3 = (const float*)d_in[ix + 10];
    const float* prW1 = (const float*)d_in[ix + 11];
    const float* prb1 = (const float*)d_in[ix + 12];
    const float* prW2 = (const float*)d_in[ix + 13];
    const float* prb2 = (const float*)d_in[ix + 14];
    const float* prW3 = (const float*)d_in[ix + 15];
    const float* prb3 = (const float*)d_in[ix + 16];

    int n = in_sizes[ix] / E;
    int W = in_sizes[ix + 4] / D;
    int nb_op = (n + 127) / 128;
    int nb_pr = D / 4;
    float* out_ops = (float*)d_out;
    float* out_pr  = out_ops + n;
    (void)out_size;

    cudaFuncSetAttribute(k_op,  cudaFuncAttributeMaxDynamicSharedMemorySize, OP_TOTAL);
    cudaFuncSetAttribute(k_pre, cudaFuncAttributeMaxDynamicSharedMemorySize, PRE_SMEM);

    int grid_pre = D / 8 + D / 16 + 3;
    k_pre<<<grid_pre, 512, PRE_SMEM>>>(y, opW1, opb1, prW1, prb1, z, num_ops, D);
    k_op<<<nb_pr + nb_op, 256, OP_TOTAL>>>(x, opW2, opb2, opW3, opb3, omsk, n, nb_pr,
                                           prW1, prW2, prb2, prW3, prb3, pmsk,
                                           out_ops, out_pr, W);
    int n4b = ((n >> 2) + 255) / 256;
    if (n4b < 1) n4b = 1;
    if (n4b > 296) n4b = 296;
    k_norm<<<n4b, 256>>>(out_ops, n, nb_op);
}

// round 11
// speedup vs baseline: 1.3377x; 1.3377x over previous
#include <cuda_runtime.h>
#include <cuda_bf16.h>
#include <math.h>

#define E      256
#define H1     32
#define H2     16
#define MAXD   1024
#define MAXN   (1024*100)

typedef unsigned long long ull;

// ---------------- device scratch ----------------
__device__ int      g_dagids[MAXN];
__device__ float    g_yop[MAXD * H1];
__device__ float    g_ypr[MAXD * H1];
__device__ float    g_czop[H1];
__device__ float    g_czpr[H1];
__device__ float    g_partials[2048];
__device__ ull      g_wpk[4096];       // opW1 x-part pairs: [k2][j] -> (W[2k2][j], W[2k2+1][j])

__device__ __forceinline__ ull ffma2(ull a, ull b, ull c) {
    ull d;
    asm("fma.rn.f32x2 %0, %1, %2, %3;" : "=l"(d) : "l"(a), "l"(b), "l"(c));
    return d;
}
__device__ __forceinline__ ull pack2(float lo, float hi) {
    return (ull)__float_as_uint(lo) | ((ull)__float_as_uint(hi) << 32);
}
__device__ __forceinline__ float unpack_sum(ull v) {
    return __uint_as_float((unsigned)(v & 0xffffffffu)) +
           __uint_as_float((unsigned)(v >> 32));
}

// ---------------- K1 (512 thr): y-precompute + dagfill + repack + cz ----------------
#define PRE_SMEM (32768 + 32768 + 8192)
__global__ void __launch_bounds__(512)
k_pre(const float* __restrict__ y,
      const float* __restrict__ opW1, const float* __restrict__ opb1,
      const float* __restrict__ prW1, const float* __restrict__ prb1,
      const float* __restrict__ z,
      const int* __restrict__ num_ops, int D)
{
    extern __shared__ unsigned char sm_raw[];
    int nbY = D / 8;
    int nbF = D / 16;
    int tid = threadIdx.x;
    int b = blockIdx.x;

    if (b < nbY) {
        float* swop = (float*)sm_raw;                 // [256][32]
        float* swpr = (float*)(sm_raw + 32768);       // [256][32]
        float* sy   = (float*)(sm_raw + 65536);       // [8][256]
        int d0 = b * 8;
        {
            const float4* s1 = (const float4*)(opW1 + E * H1);
            const float4* s2 = (const float4*)(prW1 + H1);
            float4* d1 = (float4*)swop;
            float4* d2 = (float4*)swpr;
            #pragma unroll 4
            for (int i = tid; i < 2048; i += 512) { d1[i] = s1[i]; d2[i] = s2[i]; }
            const float4* ys = (const float4*)(y + (size_t)d0 * E);
            float4* yd = (float4*)sy;
            if (tid < 512) yd[tid] = ys[tid];
        }
        __syncthreads();
        int warp = tid >> 5, lane = tid & 31;
        int dag = warp & 7, br = warp >> 3;
        const float* w = br ? swpr : swop;
        const float* yr = sy + dag * 256;
        float a0 = 0.f, a1 = 0.f, a2 = 0.f, a3 = 0.f;
        #pragma unroll 8
        for (int k = 0; k < 256; k += 4) {
            a0 = fmaf(yr[k],     w[(k)     * 32 + lane], a0);
            a1 = fmaf(yr[k + 1], w[(k + 1) * 32 + lane], a1);
            a2 = fmaf(yr[k + 2], w[(k + 2) * 32 + lane], a2);
            a3 = fmaf(yr[k + 3], w[(k + 3) * 32 + lane], a3);
        }
        float v = (a0 + a1) + (a2 + a3);
        if (br) g_ypr[(d0 + dag) * H1 + lane] = v;
        else    g_yop[(d0 + dag) * H1 + lane] = v;
        return;
    }
    if (b < nbY + nbF) {
        __shared__ int sc[256];
        __shared__ int sstart[17];
        int fb = b - nbY, d0 = fb * 16;
        if (tid < 256) {
            int a = 0;
            #pragma unroll
            for (int q = 0; q < 4; q++) {
                int idx = tid * 4 + q;
                a += (idx < D) ? num_ops[idx] : 0;
            }
            sc[tid] = a;
        }
        __syncthreads();
        #pragma unroll
        for (int off = 1; off < 256; off <<= 1) {
            int v = (tid < 256 && tid >= off) ? sc[tid - off] : 0;
            __syncthreads();
            if (tid < 256) sc[tid] += v;
            __syncthreads();
        }
        if (tid <= 16) {
            int d = d0 + tid;
            int s = (d >> 2) ? sc[(d >> 2) - 1] : 0;
            for (int q = d & ~3; q < d; q++) s += num_ops[q];
            sstart[tid] = s;
        }
        __syncthreads();
        for (int dd = 0; dd < 16; dd++) {
            int s = sstart[dd], e = sstart[dd + 1];
            for (int i = s + tid; i < e; i += 512) g_dagids[i] = d0 + dd;
        }
        return;
    }
    if (b == nbY + nbF) {
        // repack: g_wpk[k2*32 + j] = (W[2k2][j], W[2k2+1][j])
        for (int idx = tid; idx < 4096; idx += 512) {
            int k2 = idx >> 5, j = idx & 31;
            g_wpk[idx] = pack2(opW1[(2 * k2) * H1 + j],
                               opW1[(2 * k2 + 1) * H1 + j]);
        }
        return;
    }
    {
        __shared__ float sred[256];
        int br = b - (nbY + nbF + 1);
        const float* W  = br ? prW1 : opW1;
        const float* b1 = br ? prb1 : opb1;
        int off = br ? (1 + E) : (2 * E);
        if (tid < 256) {
            int j = tid & 31, c = tid >> 5;
            float a0 = 0.f, a1 = 0.f, a2 = 0.f, a3 = 0.f;
            #pragma unroll
            for (int r = 0; r < 8; r++) {
                int k = c * 32 + r * 4;
                a0 = fmaf(z[k],     W[(off + k) * H1 + j],     a0);
                a1 = fmaf(z[k + 1], W[(off + k + 1) * H1 + j], a1);
                a2 = fmaf(z[k + 2], W[(off + k + 2) * H1 + j], a2);
                a3 = fmaf(z[k + 3], W[(off + k + 3) * H1 + j], a3);
            }
            sred[tid] = (a0 + a1) + (a2 + a3);
        }
        __syncthreads();
        if (tid < 32) {
            float s = b1[tid];
            #pragma unroll
            for (int cc = 0; cc < 8; cc++) s += sred[tid + 32 * cc];
            if (br) g_czpr[tid] = s;
            else    g_czop[tid] = s;
        }
    }
}

// ---------------- K2: op MLP (register-tiled SGEMM style) + prlvl at tail ----------------
#define OP_SW    0                       // 4096 ull = 32768 (w pairs [k2][j])
#define OP_SX    32768                   // 3 x 1024 float4 cells = 49152
#define OP_SH    81920                   // 128 x 33 f = 16896
#define OP_SW2   98816                   // 512 f = 2048
#define OP_SW3   100864
#define OP_SB2   100928
#define OP_SRED  100992
#define OP_TOTAL 101024
__global__ void __launch_bounds__(256, 2)
k_op(const float* __restrict__ x,
     const float* __restrict__ opW2, const float* __restrict__ opb2,
     const float* __restrict__ opW3, const float* __restrict__ opb3,
     const float* __restrict__ omsk, int n, int nb_op,
     const float* __restrict__ prW1, const float* __restrict__ prW2,
     const float* __restrict__ prb2, const float* __restrict__ prW3,
     const float* __restrict__ prb3, const float* __restrict__ pmsk,
     float* __restrict__ out_ops, float* __restrict__ out_pr, int W)
{
    extern __shared__ unsigned char sm_raw[];
    int tid = threadIdx.x;

    if (blockIdx.x >= nb_op) {
        // ---------- prlvl: 4 dags per block, W=64 workers ----------
        float* sm   = (float*)sm_raw;
        float* sYP  = sm;          // [4][32]
        float* sr0  = sm + 128;
        float* sW2p = sm + 160;    // [512]
        float* sW3p = sm + 672;
        float* sb2p = sm + 688;
        float* red  = sm + 704;    // [4][64]
        int pb = blockIdx.x - nb_op;
        int d0 = pb * 4, g = tid >> 6, wk = tid & 63;
        int dag = d0 + g;

        if (tid < 128) {
            int gg = tid >> 5, j = tid & 31;
            sYP[gg * 32 + j] = g_ypr[(d0 + gg) * H1 + j] + g_czpr[j];
        }
        if (tid < H1) sr0[tid] = prW1[tid];
        for (int i = tid; i < H1 * H2; i += 256) sW2p[i] = prW2[i];
        if (tid < H2) { sW3p[tid] = prW3[tid]; sb2p[tid] = prb2[tid]; }
        __syncthreads();

        float lim = (float)(wk + 1);
        float h2[H2];
        #pragma unroll
        for (int m = 0; m < H2; m++) h2[m] = sb2p[m];
        #pragma unroll 4
        for (int j = 0; j < H1; j++) {
            float h1 = fmaxf(sYP[g * 32 + j] + lim * sr0[j], 0.f);
            #pragma unroll
            for (int m = 0; m < H2; m++) h2[m] += h1 * sW2p[j * H2 + m];
        }
        float lg = prb3[0];
        #pragma unroll
        for (int m = 0; m < H2; m++) lg += fmaxf(h2[m], 0.f) * sW3p[m];
        lg -= (1.f - pmsk[(size_t)dag * W + wk]) * 1000.f;

        red[g * 64 + wk] = lg;
        __syncthreads();
        for (int st = 32; st > 0; st >>= 1) {
            if (wk < st) red[g * 64 + wk] = fmaxf(red[g * 64 + wk], red[g * 64 + wk + st]);
            __syncthreads();
        }
        float mx = red[g * 64];
        __syncthreads();
        float ev = expf(lg - mx);
        red[g * 64 + wk] = ev;
        __syncthreads();
        for (int st = 32; st > 0; st >>= 1) {
            if (wk < st) red[g * 64 + wk] += red[g * 64 + wk + st];
            __syncthreads();
        }
        out_pr[(size_t)dag * W + wk] = ev / red[g * 64];
        return;
    }

    // ---------- op branch ----------
    // warp tile: 32 ops x 16 j. lane: og = lane>>2 (0..7), jg = lane&3.
    // thread tile: ops {opb + og + 8r}, j {jh*16 + jg*4 + q}.
    ull*    sw   = (ull*)(sm_raw + OP_SW);
    float4* sx   = (float4*)(sm_raw + OP_SX);      // 3 bufs x 1024 cells; cell(c4,p) at c4*128 + (p^c4)
    float*  sH   = (float*)(sm_raw + OP_SH);       // [128][33]
    float*  sW2  = (float*)(sm_raw + OP_SW2);
    float*  sW3  = (float*)(sm_raw + OP_SW3);
    float*  sb2  = (float*)(sm_raw + OP_SB2);
    float*  sRed = (float*)(sm_raw + OP_SRED);

    int base = blockIdx.x * 128;
    int warp = tid >> 5, lane = tid & 31;
    int og = lane >> 2, jg = lane & 3;
    int jh = warp & 1;
    int opb = (warp >> 1) * 32;
    const float4* xg = (const float4*)x;

    // stage packed W1 pairs + layer-2/3 weights
    {
        const float4* ws = (const float4*)g_wpk;
        float4* wd = (float4*)sw;
        #pragma unroll 4
        for (int i = tid; i < 2048; i += 256) wd[i] = ws[i];
    }
    for (int i = tid; i < H1 * H2; i += 256) sW2[i] = opW2[i];
    if (tid < H2) { sW3[tid] = opW3[tid]; sb2[tid] = opb2[tid]; }

    // staging addresses: idx = tid + 256r -> gop = idx>>3, col = idx&7
    const float4* gp[4];
    int scell[4];
    #pragma unroll
    for (int r = 0; r < 4; r++) {
        int idx = tid + 256 * r;
        int gop = idx >> 3, col = idx & 7;
        int gi = min(base + gop, n - 1);
        gp[r] = xg + (size_t)gi * 64 + col;
        scell[r] = col * 128 + (gop ^ col);
    }

    float4 pf[4];
    #pragma unroll
    for (int r = 0; r < 4; r++) pf[r] = gp[r][0];
    #pragma unroll
    for (int r = 0; r < 4; r++) sx[scell[r]] = pf[r];
    __syncthreads();

    ull acc[16];
    #pragma unroll
    for (int u = 0; u < 16; u++) acc[u] = 0ull;

    int j0 = jh * 16 + jg * 4;
    for (int c = 0; c < 8; c++) {
        if (c < 7) {
            #pragma unroll
            for (int r = 0; r < 4; r++) pf[r] = gp[r][(c + 1) * 8];
        }
        const ulonglong2* xbuf = (const ulonglong2*)(sx + (c % 3) * 1024);
        #pragma unroll
        for (int c4 = 0; c4 < 8; c4++) {
            ulonglong2 xv0 = xbuf[c4 * 128 + ((opb + og)      ^ c4)];
            ulonglong2 xv1 = xbuf[c4 * 128 + ((opb + og + 8)  ^ c4)];
            ulonglong2 xv2 = xbuf[c4 * 128 + ((opb + og + 16) ^ c4)];
            ulonglong2 xv3 = xbuf[c4 * 128 + ((opb + og + 24) ^ c4)];
            int k2b = (c * 8 + c4) * 2;
            #pragma unroll
            for (int h = 0; h < 2; h++) {
                const ulonglong2* wrow = (const ulonglong2*)(sw + (k2b + h) * 32 + j0);
                ulonglong2 wa = wrow[0];   // j pairs q0,q1
                ulonglong2 wb = wrow[1];   // j pairs q2,q3
                ull x0 = h ? xv0.y : xv0.x;
                ull x1 = h ? xv1.y : xv1.x;
                ull x2 = h ? xv2.y : xv2.x;
                ull x3 = h ? xv3.y : xv3.x;
                acc[0]  = ffma2(x0, wa.x, acc[0]);
                acc[1]  = ffma2(x0, wa.y, acc[1]);
                acc[2]  = ffma2(x0, wb.x, acc[2]);
                acc[3]  = ffma2(x0, wb.y, acc[3]);
                acc[4]  = ffma2(x1, wa.x, acc[4]);
                acc[5]  = ffma2(x1, wa.y, acc[5]);
                acc[6]  = ffma2(x1, wb.x, acc[6]);
                acc[7]  = ffma2(x1, wb.y, acc[7]);
                acc[8]  = ffma2(x2, wa.x, acc[8]);
                acc[9]  = ffma2(x2, wa.y, acc[9]);
                acc[10] = ffma2(x2, wb.x, acc[10]);
                acc[11] = ffma2(x2, wb.y, acc[11]);
                acc[12] = ffma2(x3, wa.x, acc[12]);
                acc[13] = ffma2(x3, wa.y, acc[13]);
                acc[14] = ffma2(x3, wb.x, acc[14]);
                acc[15] = ffma2(x3, wb.y, acc[15]);
            }
        }
        if (c < 7) {
            float4* dst = sx + ((c + 1) % 3) * 1024;
            #pragma unroll
            for (int r = 0; r < 4; r++) dst[scell[r]] = pf[r];
            __syncthreads();
        }
    }

    // raw sums -> sH[op][j]
    __syncthreads();
    #pragma unroll
    for (int r = 0; r < 4; r++) {
        int op = opb + og + 8 * r;
        #pragma unroll
        for (int q = 0; q < 4; q++)
            sH[op * 33 + j0 + q] = unpack_sum(acc[r * 4 + q]);
    }
    __syncthreads();

    // ypc add + relu: warp w owns rows w*16 .. w*16+15 (lane = j)
    {
        float czv = g_czop[lane];
        #pragma unroll 4
        for (int u = 0; u < 16; u++) {
            int op = warp * 16 + u;
            int i = min(base + op, n - 1);
            float ypc = g_yop[g_dagids[i] * H1 + lane] + czv;
            sH[op * 33 + lane] = fmaxf(sH[op * 33 + lane] + ypc, 0.f);
        }
    }
    __syncwarp();

    // layers 2+3: lane -> (op o2 = lane>>1 within warp's 16, half m2 = lane&1)
    float* sHw = sH + warp * 16 * 33;
    int o2 = lane >> 1, m2 = lane & 1;
    float h2[8];
    #pragma unroll
    for (int q = 0; q < 8; q++) h2[q] = sb2[m2 * 8 + q];
    const float* hrow = sHw + o2 * 33;
    #pragma unroll 8
    for (int j = 0; j < H1; j++) {
        float h = hrow[j];
        #pragma unroll
        for (int q = 0; q < 8; q++) h2[q] += h * sW2[j * H2 + m2 * 8 + q];
    }
    float part = 0.f;
    #pragma unroll
    for (int q = 0; q < 8; q++) part += fmaxf(h2[q], 0.f) * sW3[m2 * 8 + q];
    part += __shfl_xor_sync(0xffffffffu, part, 1);

    float e = 0.f;
    {
        int i = base + warp * 16 + o2;
        if (m2 == 0 && i < n) {
            float lg = part + opb3[0] - (1.f - omsk[i]) * 1000.f;
            e = expf(lg);
            out_ops[i] = e;
        }
    }
    e += __shfl_xor_sync(0xffffffffu, e, 1);
    e += __shfl_xor_sync(0xffffffffu, e, 2);
    e += __shfl_xor_sync(0xffffffffu, e, 4);
    e += __shfl_xor_sync(0xffffffffu, e, 8);
    e += __shfl_xor_sync(0xffffffffu, e, 16);
    if (lane == 0) sRed[warp] = e;
    __syncthreads();
    if (tid == 0) {
        float sum = 0.f;
        #pragma unroll
        for (int w = 0; w < 8; w++) sum += sRed[w];
        g_partials[blockIdx.x] = sum;
    }
}

// ---------------- K3: reduce partials + normalize (float4) ----------------
__global__ void __launch_bounds__(256)
k_norm(float* __restrict__ out_ops, int n, int nb_op)
{
    __shared__ float red[256];
    int t = threadIdx.x;
    float s = 0.f;
    for (int q = t; q < nb_op; q += 256) s += g_partials[q];
    red[t] = s;
    __syncthreads();
    for (int st = 128; st > 0; st >>= 1) {
        if (t < st) red[t] += red[t + st];
        __syncthreads();
    }
    float inv = 1.f / red[0];
    int n4 = n >> 2;
    float4* o4 = (float4*)out_ops;
    for (int i = blockIdx.x * 256 + t; i < n4; i += gridDim.x * 256) {
        float4 v = o4[i];
        v.x *= inv; v.y *= inv; v.z *= inv; v.w *= inv;
        o4[i] = v;
    }
    if (blockIdx.x == 0) {
        for (int i = (n & ~3) + t; i < n; i += 256) out_ops[i] *= inv;
    }
}

// ---------------- launch ----------------
extern "C" void kernel_launch(void* const* d_in, const int* in_sizes, int n_in,
                              void* d_out, int out_size)
{
    int ix = -1;
    for (int i = 0; i < n_in; i++) {
        if (in_sizes[i] == MAXN * E) { ix = i; break; }
    }
    if (ix < 0) return;

    const int*   num_ops = (const int*)d_in[0];
    int D = in_sizes[0];
    const float* x    = (const float*)d_in[ix + 0];
    const float* y    = (const float*)d_in[ix + 1];
    const float* z    = (const float*)d_in[ix + 2];
    const float* omsk = (const float*)d_in[ix + 3];
    const float* pmsk = (const float*)d_in[ix + 4];
    const float* opW1 = (const float*)d_in[ix + 5];
    const float* opb1 = (const float*)d_in[ix + 6];
    const float* opW2 = (const float*)d_in[ix + 7];
    const float* opb2 = (const float*)d_in[ix + 8];
    const float* opW3 = (const float*)d_in[ix + 9];
    const float* opb3 = (const float*)d_in[ix + 10];
    const float* prW1 = (const float*)d_in[ix + 11];
    const float* prb1 = (const float*)d_in[ix + 12];
    const float* prW2 = (const float*)d_in[ix + 13];
    const float* prb2 = (const float*)d_in[ix + 14];
    const float* prW3 = (const float*)d_in[ix + 15];
    const float* prb3 = (const float*)d_in[ix + 16];

    int n = in_sizes[ix] / E;
    int W = in_sizes[ix + 4] / D;
    int nb_op = (n + 127) / 128;
    int nb_pr = D / 4;
    float* out_ops = (float*)d_out;
    float* out_pr  = out_ops + n;
    (void)out_size;

    cudaFuncSetAttribute(k_op,  cudaFuncAttributeMaxDynamicSharedMemorySize, OP_TOTAL);
    cudaFuncSetAttribute(k_pre, cudaFuncAttributeMaxDynamicSharedMemorySize, PRE_SMEM);

    int grid_pre = D / 8 + D / 16 + 3;
    k_pre<<<grid_pre, 512, PRE_SMEM>>>(y, opW1, opb1, prW1, prb1, z, num_ops, D);
    k_op<<<nb_op + nb_pr, 256, OP_TOTAL>>>(x, opW2, opb2, opW3, opb3, omsk, n, nb_op,
                                           prW1, prW2, prb2, prW3, prb3, pmsk,
                                           out_ops, out_pr, W);
    int n4b = ((n >> 2) + 255) / 256;
    if (n4b < 1) n4b = 1;
    if (n4b > 296) n4b = 296;
    k_norm<<<n4b, 256>>>(out_ops, n, nb_op);
}